// round 2
// baseline (speedup 1.0000x reference)
#include <cuda_runtime.h>
#include <cuda_bf16.h>
#include <cstddef>

// Problem constants
#define N_TOK   32768        // B*T = 8*4096
#define DIM     128
#define KCODES  1024
#define NCB     8
#define M_TILE  64           // tokens per block
#define KC      128          // codes per smem chunk
#define TPB     256
#define GRID_MAIN (N_TOK / M_TILE)   // 512

// Scratch (no allocations allowed -> device globals)
__device__ float g_wn[NCB * KCODES];    // ||w_k||^2  (FULL norm, matches reference)
__device__ float g_part[GRID_MAIN];     // per-block loss partial sums

// ---------------------------------------------------------------------------
// packed f32x2 FMA (PTX-only path; 2x throughput vs FFMA-3reg on sm_103a)
// ---------------------------------------------------------------------------
__device__ __forceinline__ unsigned long long ffma2(unsigned long long a,
                                                    unsigned long long b,
                                                    unsigned long long c) {
    unsigned long long d;
    asm("fma.rn.f32x2 %0, %1, %2, %3;" : "=l"(d) : "l"(a), "l"(b), "l"(c));
    return d;
}
__device__ __forceinline__ void unpack2(unsigned long long v, float& lo, float& hi) {
    asm("mov.b64 {%0, %1}, %2;" : "=f"(lo), "=f"(hi) : "l"(v));
}

// ---------------------------------------------------------------------------
// Shared memory layout (dynamic; ~107 KB)
// ---------------------------------------------------------------------------
struct SB {
    float2 res[M_TILE][DIM / 2 + 1];   // residual, row padded (conflict-free)
    float2 code[KC][DIM / 2 + 1];      // staged code chunk
    float  wn[KC];                     // ||w||^2 for chunk
    float  rr[M_TILE];                 // ||r||^2 per token (this step)
    float  bestU[M_TILE][16];
    int    bestI[M_TILE][16];
    int    idx[M_TILE];
    float  red[TPB];
};

extern __shared__ char smraw[];

// ---------------------------------------------------------------------------
// Kernel 1: ||w||^2 per code. One warp per code; lane-strided partials + xor
// tree (same combination pattern XLA's GPU warp row-reduce produces at lane0).
// ---------------------------------------------------------------------------
__global__ void wnorm_kernel(const float* __restrict__ cb) {
    int gwarp = (blockIdx.x * blockDim.x + threadIdx.x) >> 5;
    int lane  = threadIdx.x & 31;
    if (gwarp >= NCB * KCODES) return;
    const float* w = cb + (size_t)gwarp * DIM;
    float s = 0.f;
    #pragma unroll
    for (int i = 0; i < DIM / 32; ++i) {
        float v = w[lane + 32 * i];
        s = __fmaf_rn(v, v, s);
    }
    #pragma unroll
    for (int o = 16; o > 0; o >>= 1) s = __fadd_rn(s, __shfl_xor_sync(0xFFFFFFFFu, s, o));
    if (lane == 0) g_wn[gwarp] = s;
}

// ---------------------------------------------------------------------------
// Kernel 2: main residual-VQ kernel. Each block owns 64 tokens end-to-end.
//
// Distance emulates the reference's fp32 rounding chain exactly:
//   u_k = fl32( fl32(rr - 2*m_k) + ww_k )      (2*m exact -> fma == mul+sub)
// argmin with first-index tie rule (quantized ties at ulp(~128) are common
// and decide ~0.4% of codes).
// ---------------------------------------------------------------------------
__global__ __launch_bounds__(TPB) void rvq_main(
    const float* __restrict__ emb, const float* __restrict__ cb,
    float* __restrict__ out_codes, float* __restrict__ out_quant)
{
    SB* sm = reinterpret_cast<SB*>(smraw);
    const int tid  = threadIdx.x;
    const int tx   = tid & 15;    // code-group   (16 groups * 8 codes = 128)
    const int ty   = tid >> 4;    // token-group  (16 groups * 4 toks  = 64)
    const int wid  = tid >> 5;    // warp id (0..7)
    const int lane = tid & 31;
    const int n0   = blockIdx.x * M_TILE;

    // residual <- embeddings
    for (int e = tid; e < M_TILE * DIM; e += TPB) {
        int m = e >> 7, d = e & (DIM - 1);
        reinterpret_cast<float*>(&sm->res[m][0])[d] = emb[(size_t)(n0 + m) * DIM + d];
    }

    float lsum = 0.f;

    for (int c = 0; c < NCB; ++c) {
        const float* cbc = cb + (size_t)c * KCODES * DIM;

        __syncthreads();   // residual writes (init or previous update) visible

        // rr[m] = ||residual_m||^2, warp per token, lane-strided + xor tree
        #pragma unroll
        for (int t = 0; t < M_TILE / 8; ++t) {
            int m = wid * (M_TILE / 8) + t;
            const float* row = reinterpret_cast<const float*>(&sm->res[m][0]);
            float s = 0.f;
            #pragma unroll
            for (int i = 0; i < DIM / 32; ++i) {
                float v = row[lane + 32 * i];
                s = __fmaf_rn(v, v, s);
            }
            #pragma unroll
            for (int o = 16; o > 0; o >>= 1)
                s = __fadd_rn(s, __shfl_xor_sync(0xFFFFFFFFu, s, o));
            if (lane == 0) sm->rr[m] = s;
        }

        float bU[4]; int bI[4];
        #pragma unroll
        for (int i = 0; i < 4; ++i) { bU[i] = 1e30f; bI[i] = 0; }

        for (int kb = 0; kb < KCODES; kb += KC) {
            __syncthreads();   // previous tile users done (and rr writes ready)
            // stage code chunk
            for (int e = tid; e < KC * (DIM / 2); e += TPB) {
                int kl = e >> 6, d2 = e & 63;
                sm->code[kl][d2] =
                    reinterpret_cast<const float2*>(cbc + (size_t)(kb + kl) * DIM)[d2];
            }
            if (tid < KC) sm->wn[tid] = g_wn[c * KCODES + kb + tid];
            __syncthreads();

            unsigned long long acc[4][8];
            #pragma unroll
            for (int i = 0; i < 4; ++i)
                #pragma unroll
                for (int j = 0; j < 8; ++j) acc[i][j] = 0ull;

            #pragma unroll 2
            for (int d2 = 0; d2 < DIM / 2; ++d2) {
                unsigned long long a[4], b[8];
                #pragma unroll
                for (int i = 0; i < 4; ++i)
                    a[i] = *reinterpret_cast<const unsigned long long*>(
                               &sm->res[ty * 4 + i][d2]);
                #pragma unroll
                for (int j = 0; j < 8; ++j)
                    b[j] = *reinterpret_cast<const unsigned long long*>(
                               &sm->code[tx + 16 * j][d2]);
                #pragma unroll
                for (int i = 0; i < 4; ++i)
                    #pragma unroll
                    for (int j = 0; j < 8; ++j)
                        acc[i][j] = ffma2(a[i], b[j], acc[i][j]);
            }

            // u = fl(fl(rr - 2*m) + ww); argmin, first index on quantized ties.
            // Per-thread candidate k ascends across (kb, j), so strict '<'
            // keeps the first (lowest-k) minimum.
            #pragma unroll
            for (int j = 0; j < 8; ++j) {
                int   kl = tx + 16 * j;
                float wn = sm->wn[kl];
                int   k  = kb + kl;
                #pragma unroll
                for (int i = 0; i < 4; ++i) {
                    float lo, hi; unpack2(acc[i][j], lo, hi);
                    float m_ = __fadd_rn(lo, hi);
                    float rr = sm->rr[ty * 4 + i];
                    float t_ = __fmaf_rn(-2.0f, m_, rr);   // == fl(rr - 2m), 2m exact
                    float u  = __fadd_rn(t_, wn);
                    if (u < bU[i]) { bU[i] = u; bI[i] = k; }
                }
            }
        }

        __syncthreads();
        #pragma unroll
        for (int i = 0; i < 4; ++i) {
            sm->bestU[ty * 4 + i][tx] = bU[i];
            sm->bestI[ty * 4 + i][tx] = bI[i];
        }
        __syncthreads();
        if (tid < M_TILE) {
            float best = sm->bestU[tid][0];
            int   bi   = sm->bestI[tid][0];
            #pragma unroll
            for (int t = 1; t < 16; ++t) {
                float u = sm->bestU[tid][t];
                int   k = sm->bestI[tid][t];
                if (u < best || (u == best && k < bi)) { best = u; bi = k; }
            }
            sm->idx[tid] = bi;
            out_codes[(size_t)(n0 + tid) * NCB + c] = (float)bi;
        }
        __syncthreads();

        // residual update, quant accumulate (sequential, like the reference),
        // loss = sum (r_new)^2
        for (int e = tid; e < M_TILE * DIM; e += TPB) {
            int m = e >> 7, d = e & (DIM - 1);
            float w = cbc[(size_t)sm->idx[m] * DIM + d];
            float* rp = &reinterpret_cast<float*>(&sm->res[m][0])[d];
            float r = __fadd_rn(*rp, -w);
            *rp = r;
            lsum += r * r;
            size_t g = (size_t)(n0 + m) * DIM + d;
            if (c == 0) {
                out_quant[g] = w;
            } else {
                float q = __fadd_rn(out_quant[g], w);
                if (c == NCB - 1) {
                    // straight-through estimator: quantized = e + (q - e)
                    float e0 = emb[g];
                    q = __fadd_rn(e0, __fadd_rn(q, -e0));
                }
                out_quant[g] = q;
            }
        }
    }

    // deterministic block loss reduction
    __syncthreads();
    sm->red[tid] = lsum;
    __syncthreads();
    for (int s = TPB / 2; s > 0; s >>= 1) {
        if (tid < s) sm->red[tid] += sm->red[tid + s];
        __syncthreads();
    }
    if (tid == 0) g_part[blockIdx.x] = sm->red[0];
}

// ---------------------------------------------------------------------------
// Kernel 3: final deterministic loss reduction
// loss = sum(r_new^2) / (N*D) / NCB
// ---------------------------------------------------------------------------
__global__ void loss_final(float* __restrict__ out_loss) {
    __shared__ float red[GRID_MAIN];
    int t = threadIdx.x;
    red[t] = g_part[t];
    __syncthreads();
    for (int s = GRID_MAIN / 2; s > 0; s >>= 1) {
        if (t < s) red[t] += red[t + s];
        __syncthreads();
    }
    if (t == 0)
        out_loss[0] = red[0] * (1.0f / ((float)N_TOK * (float)DIM * (float)NCB));
}

// ---------------------------------------------------------------------------
extern "C" void kernel_launch(void* const* d_in, const int* in_sizes, int n_in,
                              void* d_out, int out_size) {
    const float* emb = (const float*)d_in[0];   // [8,4096,128] f32
    const float* cb  = (const float*)d_in[1];   // [8,1024,128] f32

    float* out_codes = (float*)d_out;                         // 32768*8
    float* out_quant = out_codes + (size_t)N_TOK * NCB;       // 32768*128
    float* out_loss  = out_quant + (size_t)N_TOK * DIM;       // 1

    cudaFuncSetAttribute(rvq_main, cudaFuncAttributeMaxDynamicSharedMemorySize,
                         (int)sizeof(SB));

    wnorm_kernel<<<(NCB * KCODES) / 8, 256>>>(cb);
    rvq_main<<<GRID_MAIN, TPB, sizeof(SB)>>>(emb, cb, out_codes, out_quant);
    loss_final<<<1, GRID_MAIN>>>(out_loss);
}

// round 3
// speedup vs baseline: 1.0223x; 1.0223x over previous
#include <cuda_runtime.h>
#include <cuda_bf16.h>
#include <cstddef>
#include <cstdint>

// Problem constants
#define N_TOK   32768        // B*T = 8*4096
#define DIM     128
#define KCODES  1024
#define NCB     8
#define M_TILE  128          // tokens per block
#define KC      128          // codes per smem chunk
#define TPB     256
#define GRID_MAIN (N_TOK / M_TILE)            // 256
#define NCHUNK  (NCB * KCODES / KC)           // 64 linear chunks (codebooks contiguous)

// Scratch (no allocations allowed -> device globals)
__device__ float g_wn[NCB * KCODES];    // ||w_k||^2 (full norm, matches reference)
__device__ float g_part[GRID_MAIN];     // per-block loss partial sums

// ---------------------------------------------------------------------------
// packed f32x2 FMA (PTX-only; 2x throughput vs FFMA-3reg on sm_103a)
// ---------------------------------------------------------------------------
__device__ __forceinline__ unsigned long long ffma2(unsigned long long a,
                                                    unsigned long long b,
                                                    unsigned long long c) {
    unsigned long long d;
    asm("fma.rn.f32x2 %0, %1, %2, %3;" : "=l"(d) : "l"(a), "l"(b), "l"(c));
    return d;
}
__device__ __forceinline__ void unpack2(unsigned long long v, float& lo, float& hi) {
    asm("mov.b64 {%0, %1}, %2;" : "=f"(lo), "=f"(hi) : "l"(v));
}
__device__ __forceinline__ void cp_async8(uint32_t dst_smem, const void* src) {
    asm volatile("cp.async.ca.shared.global [%0], [%1], 8;\n"
                 :: "r"(dst_smem), "l"(src));
}
#define CP_COMMIT() asm volatile("cp.async.commit_group;\n" ::: "memory")
#define CP_WAIT(n)  asm volatile("cp.async.wait_group %0;\n" :: "n"(n) : "memory")

// ---------------------------------------------------------------------------
// Shared memory (~210 KB): res/code rows padded to 65 float2 (row stride
// == 2 banks mod 32 -> conflict-free LDS.64 for both a- and b-operands).
// ---------------------------------------------------------------------------
struct SB {
    float2 res[M_TILE][DIM / 2 + 1];        // 66.5 KB residual
    float2 code[2][KC][DIM / 2 + 1];        // 133 KB  double-buffered chunk
    float  wn[KCODES];                      // 4 KB    ||w||^2, current codebook
    float  rr[M_TILE];                      // ||r||^2 per token (this step)
    int    idx[M_TILE];                     // chosen code, current step
    int    codes_all[NCB][M_TILE];          // 4 KB    code history (quant pass)
    float  red[TPB];
};

extern __shared__ char smraw[];

// ---------------------------------------------------------------------------
// Kernel 1: ||w||^2 per code (warp per code; lane-strided + xor tree)
// ---------------------------------------------------------------------------
__global__ void wnorm_kernel(const float* __restrict__ cb) {
    int gwarp = (blockIdx.x * blockDim.x + threadIdx.x) >> 5;
    int lane  = threadIdx.x & 31;
    if (gwarp >= NCB * KCODES) return;
    const float* w = cb + (size_t)gwarp * DIM;
    float s = 0.f;
    #pragma unroll
    for (int i = 0; i < DIM / 32; ++i) {
        float v = w[lane + 32 * i];
        s = __fmaf_rn(v, v, s);
    }
    #pragma unroll
    for (int o = 16; o > 0; o >>= 1)
        s = __fadd_rn(s, __shfl_xor_sync(0xFFFFFFFFu, s, o));
    if (lane == 0) g_wn[gwarp] = s;
}

// ---------------------------------------------------------------------------
// stage one 64KB code chunk (128 rows x 64 float2) via cp.async, 8B grain.
// Chunks are contiguous in gmem (codebooks are contiguous rows).
// ---------------------------------------------------------------------------
__device__ __forceinline__ void stage_chunk(SB* sm, const float2* cb2,
                                            int t, int tid) {
    const float2* src = cb2 + (size_t)t * (KC * DIM / 2);
    int buf = t & 1;
    #pragma unroll
    for (int r = 0; r < (KC * DIM / 2) / TPB; ++r) {   // 32 per thread
        int e  = tid + r * TPB;
        int kl = e >> 6, d2 = e & 63;
        uint32_t dst = (uint32_t)__cvta_generic_to_shared(&sm->code[buf][kl][d2]);
        cp_async8(dst, src + e);
    }
    CP_COMMIT();
}

// ---------------------------------------------------------------------------
// Kernel 2: main residual-VQ. Block owns 128 tokens end-to-end.
// Scoring chain is byte-identical to the validated round-2 kernel:
//   m  = fadd(lo, hi) of ffma2 chain over d2
//   u  = fadd( fma(-2, m, rr), wn )   ; argmin, first-index ties
// ---------------------------------------------------------------------------
__global__ __launch_bounds__(TPB, 1) void rvq_main(
    const float* __restrict__ emb, const float* __restrict__ cb,
    float* __restrict__ out_codes, float* __restrict__ out_quant)
{
    SB* sm = reinterpret_cast<SB*>(smraw);
    const int tid  = threadIdx.x;
    const int tx   = tid & 15;    // code group (16 x 8 codes = 128)
    const int ty   = tid >> 4;    // token group (16 x 8 tokens = 128)
    const int wid  = tid >> 5;
    const int lane = tid & 31;
    const int n0   = blockIdx.x * M_TILE;
    const float2* cb2 = reinterpret_cast<const float2*>(cb);

    // residual <- embeddings
    for (int e = tid; e < M_TILE * DIM; e += TPB) {
        int m = e >> 7, d = e & (DIM - 1);
        reinterpret_cast<float*>(&sm->res[m][0])[d] = emb[(size_t)(n0 + m) * DIM + d];
    }

    // prefetch chunk 0
    stage_chunk(sm, cb2, 0, tid);

    float lsum = 0.f;

    for (int c = 0; c < NCB; ++c) {
        const float* cbc = cb + (size_t)c * KCODES * DIM;

        __syncthreads();   // residual writes (init / previous update) visible

        // rr[m] = ||residual_m||^2 (warp rows, lane-strided + xor tree)
        #pragma unroll
        for (int t = 0; t < M_TILE / 8; ++t) {
            int m = wid * (M_TILE / 8) + t;
            const float* row = reinterpret_cast<const float*>(&sm->res[m][0]);
            float s = 0.f;
            #pragma unroll
            for (int i = 0; i < DIM / 32; ++i) {
                float v = row[lane + 32 * i];
                s = __fmaf_rn(v, v, s);
            }
            #pragma unroll
            for (int o = 16; o > 0; o >>= 1)
                s = __fadd_rn(s, __shfl_xor_sync(0xFFFFFFFFu, s, o));
            if (lane == 0) sm->rr[m] = s;
        }
        // stage ||w||^2 for this codebook
        for (int e = tid; e < KCODES; e += TPB)
            sm->wn[e] = g_wn[c * KCODES + e];

        float bU[8]; int bI[8];
        #pragma unroll
        for (int i = 0; i < 8; ++i) { bU[i] = 1e30f; bI[i] = 0; }

        for (int tch = c * 8; tch < c * 8 + 8; ++tch) {
            const int kb  = (tch & 7) * KC;
            const int buf = tch & 1;

            // prefetch next chunk into the other buffer (safe: end-of-iter
            // sync of tch-1 guarantees its compute finished)
            if (tch + 1 < NCHUNK) { stage_chunk(sm, cb2, tch + 1, tid); CP_WAIT(1); }
            else                  { CP_WAIT(0); }
            __syncthreads();      // chunk tch visible everywhere (+ rr/wn on first)

            float rrv[8];
            #pragma unroll
            for (int i = 0; i < 8; ++i) rrv[i] = sm->rr[ty * 8 + i];

            unsigned long long acc[8][8];
            #pragma unroll
            for (int i = 0; i < 8; ++i)
                #pragma unroll
                for (int j = 0; j < 8; ++j) acc[i][j] = 0ull;

            #pragma unroll 2
            for (int d2 = 0; d2 < DIM / 2; ++d2) {
                unsigned long long b[8];
                #pragma unroll
                for (int j = 0; j < 8; ++j)
                    b[j] = *reinterpret_cast<const unsigned long long*>(
                               &sm->code[buf][tx + 16 * j][d2]);
                #pragma unroll
                for (int i = 0; i < 8; ++i) {
                    unsigned long long a =
                        *reinterpret_cast<const unsigned long long*>(
                            &sm->res[ty * 8 + i][d2]);
                    #pragma unroll
                    for (int j = 0; j < 8; ++j)
                        acc[i][j] = ffma2(a, b[j], acc[i][j]);
                }
            }

            // u = fl(fl(rr - 2m) + ww); argmin, first index on ties.
            // k ascends over (tch, j) per thread -> strict '<' keeps lowest k.
            #pragma unroll
            for (int j = 0; j < 8; ++j) {
                int   kl = tx + 16 * j;
                float wn = sm->wn[kb + kl];
                int   k  = kb + kl;
                #pragma unroll
                for (int i = 0; i < 8; ++i) {
                    float lo, hi; unpack2(acc[i][j], lo, hi);
                    float m_ = __fadd_rn(lo, hi);
                    float t_ = __fmaf_rn(-2.0f, m_, rrv[i]);
                    float u  = __fadd_rn(t_, wn);
                    if (u < bU[i]) { bU[i] = u; bI[i] = k; }
                }
            }
            __syncthreads();      // compute done before anyone refills buf
        }

        // cross-thread argmin over the 16 tx lanes of each half-warp
        // ((minU, minK-on-tie) is associative & commutative -> same result
        // as the first-index linear scan)
        #pragma unroll
        for (int i = 0; i < 8; ++i) {
            float u = bU[i]; int k = bI[i];
            #pragma unroll
            for (int o = 1; o < 16; o <<= 1) {
                float ou = __shfl_xor_sync(0xFFFFFFFFu, u, o);
                int   ok = __shfl_xor_sync(0xFFFFFFFFu, k, o);
                if (ou < u || (ou == u && ok < k)) { u = ou; k = ok; }
            }
            if (tx == 0) {
                int m = ty * 8 + i;
                sm->idx[m] = k;
                sm->codes_all[c][m] = k;
                out_codes[(size_t)(n0 + m) * NCB + c] = (float)k;
            }
        }
        __syncthreads();   // idx visible to update loop

        // residual update (exact reference chain) + loss accumulation
        for (int e = tid; e < M_TILE * DIM; e += TPB) {
            int m = e >> 7, d = e & (DIM - 1);
            float w = cbc[(size_t)sm->idx[m] * DIM + d];
            float* rp = &reinterpret_cast<float*>(&sm->res[m][0])[d];
            float r = __fadd_rn(*rp, -w);
            *rp = r;
            lsum += r * r;
        }
    }

    // quantized output: q = sum_c w[idx_c] (same fl add chain as reference,
    // which starts from 0), then straight-through: out = e + (q - e)
    __syncthreads();
    for (int e = tid; e < M_TILE * DIM; e += TPB) {
        int m = e >> 7, d = e & (DIM - 1);
        float q = cb[(size_t)sm->codes_all[0][m] * DIM + d];
        #pragma unroll
        for (int c = 1; c < NCB; ++c)
            q = __fadd_rn(q, cb[(size_t)c * KCODES * DIM
                               + (size_t)sm->codes_all[c][m] * DIM + d]);
        size_t g = (size_t)(n0 + m) * DIM + d;
        float e0 = emb[g];
        out_quant[g] = __fadd_rn(e0, __fadd_rn(q, -e0));
    }

    // deterministic block loss reduction
    sm->red[tid] = lsum;
    __syncthreads();
    for (int s = TPB / 2; s > 0; s >>= 1) {
        if (tid < s) sm->red[tid] += sm->red[tid + s];
        __syncthreads();
    }
    if (tid == 0) g_part[blockIdx.x] = sm->red[0];
}

// ---------------------------------------------------------------------------
// Kernel 3: final deterministic loss reduction
// ---------------------------------------------------------------------------
__global__ void loss_final(float* __restrict__ out_loss) {
    __shared__ float red[GRID_MAIN];
    int t = threadIdx.x;
    red[t] = g_part[t];
    __syncthreads();
    for (int s = GRID_MAIN / 2; s > 0; s >>= 1) {
        if (t < s) red[t] += red[t + s];
        __syncthreads();
    }
    if (t == 0)
        out_loss[0] = red[0] * (1.0f / ((float)N_TOK * (float)DIM * (float)NCB));
}

// ---------------------------------------------------------------------------
extern "C" void kernel_launch(void* const* d_in, const int* in_sizes, int n_in,
                              void* d_out, int out_size) {
    const float* emb = (const float*)d_in[0];   // [8,4096,128] f32
    const float* cb  = (const float*)d_in[1];   // [8,1024,128] f32

    float* out_codes = (float*)d_out;                         // 32768*8
    float* out_quant = out_codes + (size_t)N_TOK * NCB;       // 32768*128
    float* out_loss  = out_quant + (size_t)N_TOK * DIM;       // 1

    cudaFuncSetAttribute(rvq_main, cudaFuncAttributeMaxDynamicSharedMemorySize,
                         (int)sizeof(SB));

    wnorm_kernel<<<(NCB * KCODES) / 8, 256>>>(cb);
    rvq_main<<<GRID_MAIN, TPB, sizeof(SB)>>>(emb, cb, out_codes, out_quant);
    loss_final<<<1, GRID_MAIN>>>(out_loss);
}